// round 15
// baseline (speedup 1.0000x reference)
#include <cuda_runtime.h>
#include <cuda_fp16.h>
#include <cstdint>

#define MAXN 100096
#define MAXE 3200000

// ---- scratch (device globals; no allocation allowed) ----
__device__ __half g_yhA[MAXN * 64];
__device__ __half g_selfhA[MAXN * 64];
__device__ __half g_yhB[MAXN * 64];
__device__ __half g_selfhB[MAXN * 64];
__device__ int      g_deg[MAXN];
__device__ int      g_rowptr[MAXN + 1];
__device__ int      g_cursor[MAXN];
__device__ int      g_csrc[MAXE];
__device__ unsigned g_state[256];      // lookback scan tile states
__device__ __half g_w0[128 * 128];     // fused [Wl0|Wr0] fp16, row-major [o][k]
__device__ __half g_w1[128 * 64];
__device__ __half g_w2[128 * 64];

__device__ __forceinline__ uint32_t smem_u32(const void* p) {
    uint32_t a;
    asm("{ .reg .u64 t; cvta.to.shared.u64 t, %1; cvt.u32.u64 %0, t; }" : "=r"(a) : "l"(p));
    return a;
}

// ---------------------------------------------------------------------------
// prep: weight fp32->fp16 fused images + zero deg + zero scan state
// ---------------------------------------------------------------------------
__global__ void prep_all(const float* __restrict__ Wl0, const float* __restrict__ Wr0,
                         const float* __restrict__ Wl1, const float* __restrict__ Wr1,
                         const float* __restrict__ Wl2, const float* __restrict__ Wr2,
                         __half* __restrict__ w0, __half* __restrict__ w1,
                         __half* __restrict__ w2,
                         int* __restrict__ deg, unsigned* __restrict__ state, int N) {
    int i = blockIdx.x * blockDim.x + threadIdx.x;
    if (i < 128 * 128) {
        int o = i >> 7, k = i & 127;
        float v = (o < 64) ? Wl0[o * 128 + k] : Wr0[(o - 64) * 128 + k];
        w0[i] = __float2half_rn(v);
    } else if (i < 128 * 128 + 128 * 64) {
        int j = i - 128 * 128;
        int o = j >> 6, k = j & 63;
        float v = (o < 64) ? Wl1[o * 64 + k] : Wr1[(o - 64) * 64 + k];
        w1[j] = __float2half_rn(v);
    } else if (i < 128 * 128 + 2 * 128 * 64) {
        int j = i - 128 * 128 - 128 * 64;
        int o = j >> 6, k = j & 63;
        float v = (o < 64) ? Wl2[o * 64 + k] : Wr2[(o - 64) * 64 + k];
        w2[j] = __float2half_rn(v);
    }
    if (i < N) deg[i] = 0;
    if (i < 256) state[i] = 0u;
}

// ---------------------------------------------------------------------------
// degree: int4-vectorized, 4 edges per thread
// ---------------------------------------------------------------------------
__global__ void deg_kernel(const int* __restrict__ dst, int* __restrict__ deg, int E) {
    int t = blockIdx.x * blockDim.x + threadIdx.x;
    int i4 = t * 4;
    if (i4 + 3 < E) {
        int4 d = __ldg((const int4*)dst + t);
        atomicAdd(&deg[d.x], 1);
        atomicAdd(&deg[d.y], 1);
        atomicAdd(&deg[d.z], 1);
        atomicAdd(&deg[d.w], 1);
    } else {
        for (int j = i4; j < E; j++) atomicAdd(&deg[dst[j]], 1);
    }
}

// ---------------------------------------------------------------------------
// single-kernel exclusive scan via decoupled lookback (unchanged from R14)
// ---------------------------------------------------------------------------
__global__ void scan_lookback(const int* __restrict__ deg, int* __restrict__ rowptr,
                              int* __restrict__ cursor, unsigned* __restrict__ state,
                              int N) {
    __shared__ int sh[256];
    __shared__ int s_excl;
    const unsigned FULL = 0xffffffffu;
    const int b = blockIdx.x, t = threadIdx.x;
    const int base = b * 1024 + t * 4;
    int v[4];
#pragma unroll
    for (int k = 0; k < 4; k++) v[k] = (base + k < N) ? deg[base + k] : 0;
    int tot = v[0] + v[1] + v[2] + v[3];
    sh[t] = tot;
    __syncthreads();
#pragma unroll
    for (int off = 1; off < 256; off <<= 1) {
        int x = (t >= off) ? sh[t - off] : 0;
        __syncthreads();
        sh[t] += x;
        __syncthreads();
    }
    const int blockTotal = sh[255];
    const int local_excl = sh[t] - tot;

    if (b == 0) {
        if (t == 0) {
            atomicExch(&state[0], (2u << 30) | (unsigned)blockTotal);
            s_excl = 0;
        }
    } else {
        if (t == 0)
            atomicExch(&state[b], (1u << 30) | (unsigned)blockTotal);
        if (t < 32) {
            int lane = t;
            int excl = 0;
            int tile = b - 1;
            while (true) {
                int widx = tile - lane;
                unsigned st;
                if (widx < 0) {
                    st = 2u << 30;
                } else {
                    do { st = atomicAdd(&state[widx], 0u); } while ((st >> 30) == 0u);
                }
                unsigned pm = __ballot_sync(FULL, (st >> 30) == 2u);
                int closest = __ffs(pm) - 1;
                int val = (int)(st & 0x3FFFFFFFu);
                int contrib;
                if (pm == 0) contrib = val;
                else contrib = (lane <= closest) ? val : 0;
#pragma unroll
                for (int off = 16; off > 0; off >>= 1)
                    contrib += __shfl_down_sync(FULL, contrib, off);
                excl += __shfl_sync(FULL, contrib, 0);
                if (pm) break;
                tile -= 32;
            }
            if (lane == 0) {
                s_excl = excl;
                atomicExch(&state[b], (2u << 30) | (unsigned)(excl + blockTotal));
            }
        }
    }
    __syncthreads();
    int run = s_excl + local_excl;
#pragma unroll
    for (int k = 0; k < 4; k++) {
        if (base + k < N) { rowptr[base + k] = run; cursor[base + k] = run; }
        run += v[k];
    }
    if (b == gridDim.x - 1 && t == 255) rowptr[N] = s_excl + blockTotal;
}

// ---------------------------------------------------------------------------
// merged kernel: grid (782, 3).
//   blockIdx.y < 2  : layer-0 column-split HMMA GEMM (unchanged math)
//   blockIdx.y == 2 : cursor scatter, 16 edges/thread (4 x int4, coalesced)
// Heterogeneous CTAs overlap tensor/L1 work with L2-atomic work on the SMs.
// ---------------------------------------------------------------------------
template <typename T, int KIN>
__global__ __launch_bounds__(256, 4)
void gemm_scatter(const T* __restrict__ X, const __half* __restrict__ Wimg,
                  const float* __restrict__ blv,
                  __half* __restrict__ Yh, __half* __restrict__ Sh, int N,
                  const int* __restrict__ src, const int* __restrict__ dst,
                  int* __restrict__ cursor, int* __restrict__ csrc, int E) {
    constexpr int LDA = KIN + 8;
    extern __shared__ __half sm[];

    const int t = threadIdx.x;

    if (blockIdx.y == 2) {
        // ---- scatter role: block covers edges [b*4096, b*4096+4096) ----
        const int base4 = blockIdx.x * 1024;   // int4 units
#pragma unroll
        for (int k = 0; k < 4; k++) {
            int i4 = base4 + k * 256 + t;
            int e0 = i4 * 4;
            if (e0 + 3 < E) {
                int4 s = __ldg((const int4*)src + i4);
                int4 d = __ldg((const int4*)dst + i4);
                csrc[atomicAdd(&cursor[d.x], 1)] = s.x;
                csrc[atomicAdd(&cursor[d.y], 1)] = s.y;
                csrc[atomicAdd(&cursor[d.z], 1)] = s.z;
                csrc[atomicAdd(&cursor[d.w], 1)] = s.w;
            } else if (e0 < E) {
                for (int j = e0; j < E; j++) {
                    int pos = atomicAdd(&cursor[dst[j]], 1);
                    csrc[pos] = src[j];
                }
            }
        }
        return;
    }

    // ---- GEMM role (identical to R14 gemm_cs) ----
    __half* As = sm;
    __half* Ws = sm + 128 * LDA;
    float* bls = (float*)(sm + 192 * LDA);

    const int warp = t >> 5, lane = t & 31;
    const int g = lane >> 2, tg = lane & 3;
    const int n0 = blockIdx.x * 128;
    const int half_sel = blockIdx.y;

    if (t < 64) bls[t] = blv[t];

    {
        const __half* wsrc = Wimg + (size_t)half_sel * 64 * KIN;
        constexpr int NW = 64 * KIN / 8;
        for (int c = t; c < NW; c += 256) {
            int row = c / (KIN / 8);
            int k = (c % (KIN / 8)) * 8;
            *(uint4*)&Ws[row * LDA + k] = *(const uint4*)&Wimg[0];  // placeholder, replaced below
            *(uint4*)&Ws[row * LDA + k] = *(const uint4*)&wsrc[row * KIN + k];
        }
    }
    {
        constexpr int NA = 128 * KIN / 8;
        for (int c = t; c < NA; c += 256) {
            int row = c / (KIN / 8);
            int k = (c % (KIN / 8)) * 8;
            int n = n0 + row;
            uint4 hv = make_uint4(0u, 0u, 0u, 0u);
            if (n < N) {
                if constexpr (sizeof(T) == 4) {
                    const float4* xp = (const float4*)(X + (size_t)n * KIN + k);
                    float4 v0 = xp[0], v1 = xp[1];
                    __half2 h0 = __floats2half2_rn(v0.x, v0.y);
                    __half2 h1 = __floats2half2_rn(v0.z, v0.w);
                    __half2 h2 = __floats2half2_rn(v1.x, v1.y);
                    __half2 h3 = __floats2half2_rn(v1.z, v1.w);
                    hv.x = *reinterpret_cast<uint32_t*>(&h0);
                    hv.y = *reinterpret_cast<uint32_t*>(&h1);
                    hv.z = *reinterpret_cast<uint32_t*>(&h2);
                    hv.w = *reinterpret_cast<uint32_t*>(&h3);
                } else {
                    hv = *(const uint4*)&X[(size_t)n * KIN + k];
                }
            }
            *(uint4*)&As[row * LDA + k] = hv;
        }
    }
    __syncthreads();

    float acc[8][4];
#pragma unroll
    for (int nt = 0; nt < 8; nt++)
#pragma unroll
        for (int q = 0; q < 4; q++) acc[nt][q] = 0.f;

    const uint32_t a_base = smem_u32(
        &As[(warp * 16 + (lane & 15)) * LDA + ((lane >> 4) << 3)]);
    const int grp = lane >> 3;
    const uint32_t b_base = smem_u32(
        &Ws[(((grp >> 1) << 3) + (lane & 7)) * LDA + ((grp & 1) << 3)]);
    constexpr uint32_t B_P_STRIDE = 16 * LDA * 2;

#pragma unroll
    for (int kb = 0; kb < KIN; kb += 16) {
        uint32_t a0, a1, a2, a3;
        asm volatile("ldmatrix.sync.aligned.m8n8.x4.shared.b16 {%0,%1,%2,%3}, [%4];"
                     : "=r"(a0), "=r"(a1), "=r"(a2), "=r"(a3)
                     : "r"(a_base + kb * 2));
#pragma unroll
        for (int p = 0; p < 4; p++) {
            uint32_t b0, b1, b2, b3;
            asm volatile("ldmatrix.sync.aligned.m8n8.x4.shared.b16 {%0,%1,%2,%3}, [%4];"
                         : "=r"(b0), "=r"(b1), "=r"(b2), "=r"(b3)
                         : "r"(b_base + p * B_P_STRIDE + kb * 2));
            asm volatile(
                "mma.sync.aligned.m16n8k16.row.col.f32.f16.f16.f32 "
                "{%0,%1,%2,%3}, {%4,%5,%6,%7}, {%8,%9}, {%0,%1,%2,%3};"
                : "+f"(acc[2 * p][0]), "+f"(acc[2 * p][1]),
                  "+f"(acc[2 * p][2]), "+f"(acc[2 * p][3])
                : "r"(a0), "r"(a1), "r"(a2), "r"(a3), "r"(b0), "r"(b1));
            asm volatile(
                "mma.sync.aligned.m16n8k16.row.col.f32.f16.f16.f32 "
                "{%0,%1,%2,%3}, {%4,%5,%6,%7}, {%8,%9}, {%0,%1,%2,%3};"
                : "+f"(acc[2 * p + 1][0]), "+f"(acc[2 * p + 1][1]),
                  "+f"(acc[2 * p + 1][2]), "+f"(acc[2 * p + 1][3])
                : "r"(a0), "r"(a1), "r"(a2), "r"(a3), "r"(b2), "r"(b3));
        }
    }

    const int r0 = n0 + warp * 16 + g;
    const int r1 = r0 + 8;
    if (half_sel == 0) {
#pragma unroll
        for (int nt = 0; nt < 8; nt++) {
            int col = nt * 8 + tg * 2;
            if (r0 < N) {
                __half2 h = __floats2half2_rn(acc[nt][0], acc[nt][1]);
                *reinterpret_cast<__half2*>(Yh + (size_t)r0 * 64 + col) = h;
            }
            if (r1 < N) {
                __half2 h = __floats2half2_rn(acc[nt][2], acc[nt][3]);
                *reinterpret_cast<__half2*>(Yh + (size_t)r1 * 64 + col) = h;
            }
        }
    } else {
#pragma unroll
        for (int nt = 0; nt < 8; nt++) {
            int col = nt * 8 + tg * 2;
            float bx = bls[col], by = bls[col + 1];
            if (r0 < N) {
                __half2 h = __floats2half2_rn(acc[nt][0] + bx, acc[nt][1] + by);
                *reinterpret_cast<__half2*>(Sh + (size_t)r0 * 64 + col) = h;
            }
            if (r1 < N) {
                __half2 h = __floats2half2_rn(acc[nt][2] + bx, acc[nt][3] + by);
                *reinterpret_cast<__half2*>(Sh + (size_t)r1 * 64 + col) = h;
            }
        }
    }
}

// ---------------------------------------------------------------------------
// gather helper: 8-lane group aggregates one node's neighborhood (fp16 rows)
// ---------------------------------------------------------------------------
__device__ __forceinline__ void gather_node(
    const uint4* __restrict__ Y4, const int* __restrict__ csrc,
    int beg, int end, int sl, unsigned smask, float* sums) {
    float2 acc0 = make_float2(0.f, 0.f), acc1 = make_float2(0.f, 0.f);
    float2 acc2 = make_float2(0.f, 0.f), acc3 = make_float2(0.f, 0.f);
    int idx = (beg + sl < end) ? __ldg(csrc + beg + sl) : 0;
    for (int i = beg; i < end; i += 8) {
        int nxt = (i + 8 + sl < end) ? __ldg(csrc + i + 8 + sl) : 0;
        int cnt = min(8, end - i);
        if (cnt == 8) {
            int s[8];
#pragma unroll
            for (int u = 0; u < 8; u++) s[u] = __shfl_sync(smask, idx, u, 8);
            uint4 v[8];
#pragma unroll
            for (int u = 0; u < 8; u++) v[u] = __ldg(Y4 + (size_t)s[u] * 8 + sl);
#pragma unroll
            for (int u = 0; u < 8; u++) {
                float2 f0 = __half22float2(*reinterpret_cast<__half2*>(&v[u].x));
                float2 f1 = __half22float2(*reinterpret_cast<__half2*>(&v[u].y));
                float2 f2 = __half22float2(*reinterpret_cast<__half2*>(&v[u].z));
                float2 f3 = __half22float2(*reinterpret_cast<__half2*>(&v[u].w));
                acc0.x += f0.x; acc0.y += f0.y;
                acc1.x += f1.x; acc1.y += f1.y;
                acc2.x += f2.x; acc2.y += f2.y;
                acc3.x += f3.x; acc3.y += f3.y;
            }
        } else {
            for (int j = 0; j < cnt; j++) {
                int s0 = __shfl_sync(smask, idx, j, 8);
                uint4 v = __ldg(Y4 + (size_t)s0 * 8 + sl);
                float2 f0 = __half22float2(*reinterpret_cast<__half2*>(&v.x));
                float2 f1 = __half22float2(*reinterpret_cast<__half2*>(&v.y));
                float2 f2 = __half22float2(*reinterpret_cast<__half2*>(&v.z));
                float2 f3 = __half22float2(*reinterpret_cast<__half2*>(&v.w));
                acc0.x += f0.x; acc0.y += f0.y;
                acc1.x += f1.x; acc1.y += f1.y;
                acc2.x += f2.x; acc2.y += f2.y;
                acc3.x += f3.x; acc3.y += f3.y;
            }
        }
        idx = nxt;
    }
    sums[0] = acc0.x; sums[1] = acc0.y; sums[2] = acc1.x; sums[3] = acc1.y;
    sums[4] = acc2.x; sums[5] = acc2.y; sums[6] = acc3.x; sums[7] = acc3.y;
}

// finalize helper: mean + self + BN + ReLU -> 8 fp16 packed in uint4
__device__ __forceinline__ uint4 finalize_node(
    const float* sums, float invd, const __half* __restrict__ selfh,
    const float* __restrict__ gamma, const float* __restrict__ beta,
    const float* __restrict__ mean, const float* __restrict__ var,
    size_t node, int f) {
    uint4 sp = *reinterpret_cast<const uint4*>(selfh + node * 64 + f);
    float2 s01 = __half22float2(*reinterpret_cast<__half2*>(&sp.x));
    float2 s23 = __half22float2(*reinterpret_cast<__half2*>(&sp.y));
    float2 s45 = __half22float2(*reinterpret_cast<__half2*>(&sp.z));
    float2 s67 = __half22float2(*reinterpret_cast<__half2*>(&sp.w));
    float sva[8] = {s01.x, s01.y, s23.x, s23.y, s45.x, s45.y, s67.x, s67.y};
    float4 g0 = *reinterpret_cast<const float4*>(gamma + f);
    float4 g1 = *reinterpret_cast<const float4*>(gamma + f + 4);
    float4 b0 = *reinterpret_cast<const float4*>(beta + f);
    float4 b1 = *reinterpret_cast<const float4*>(beta + f + 4);
    float4 m0 = *reinterpret_cast<const float4*>(mean + f);
    float4 m1 = *reinterpret_cast<const float4*>(mean + f + 4);
    float4 v0 = *reinterpret_cast<const float4*>(var + f);
    float4 v1 = *reinterpret_cast<const float4*>(var + f + 4);
    float ga[8] = {g0.x, g0.y, g0.z, g0.w, g1.x, g1.y, g1.z, g1.w};
    float ba[8] = {b0.x, b0.y, b0.z, b0.w, b1.x, b1.y, b1.z, b1.w};
    float ma[8] = {m0.x, m0.y, m0.z, m0.w, m1.x, m1.y, m1.z, m1.w};
    float va[8] = {v0.x, v0.y, v0.z, v0.w, v1.x, v1.y, v1.z, v1.w};
    float o[8];
#pragma unroll
    for (int k = 0; k < 8; k++)
        o[k] = fmaxf((sums[k] * invd + sva[k] - ma[k]) * rsqrtf(va[k] + 1e-5f) * ga[k] + ba[k], 0.f);
    __half2 p0 = __floats2half2_rn(o[0], o[1]);
    __half2 p1 = __floats2half2_rn(o[2], o[3]);
    __half2 p2 = __floats2half2_rn(o[4], o[5]);
    __half2 p3 = __floats2half2_rn(o[6], o[7]);
    uint4 pk;
    pk.x = *reinterpret_cast<uint32_t*>(&p0);
    pk.y = *reinterpret_cast<uint32_t*>(&p1);
    pk.z = *reinterpret_cast<uint32_t*>(&p2);
    pk.w = *reinterpret_cast<uint32_t*>(&p3);
    return pk;
}

// ---------------------------------------------------------------------------
// fused layer: agg(layer i) -> smem h tile -> HMMA (layer i+1, full 128 cols)
// ---------------------------------------------------------------------------
__global__ __launch_bounds__(256, 2)
void fused_layer(const int* __restrict__ rowptr, const int* __restrict__ csrc,
                 const __half* __restrict__ Yh_in, const __half* __restrict__ selfh_in,
                 const float* __restrict__ gamma, const float* __restrict__ beta,
                 const float* __restrict__ mean, const float* __restrict__ var,
                 const __half* __restrict__ Wimg, const float* __restrict__ blv,
                 __half* __restrict__ Yh_out, __half* __restrict__ selfh_out, int N) {
    constexpr int LDA = 72;
    extern __shared__ __half sm[];
    __half* As = sm;                            // [128][72] h tile
    __half* Ws = sm + 128 * LDA;                // [128][72] weights
    float* bls = (float*)(sm + 2 * 128 * LDA);  // [64]

    const int t = threadIdx.x;
    const int warp = t >> 5, lane = t & 31;
    const int g = lane >> 2, tg = lane & 3;
    const int n0 = blockIdx.x * 128;
    const int sl = t & 7;
    const unsigned smask = 0xffu << (t & 24);

    if (t < 64) bls[t] = blv[t];
    for (int c = t; c < 1024; c += 256) {
        int row = c >> 3, k = (c & 7) * 8;
        *(uint4*)&Ws[row * LDA + k] = *(const uint4*)&Wimg[row * 64 + k];
    }

    const uint4* Y4 = reinterpret_cast<const uint4*>(Yh_in);
#pragma unroll
    for (int r = 0; r < 4; r++) {
        int nl = r * 32 + (t >> 3);
        int node = n0 + nl;
        if (node < N) {
            int beg = rowptr[node], end = rowptr[node + 1];
            float sums[8];
            gather_node(Y4, csrc, beg, end, sl, smask, sums);
            float invd = 1.f / fmaxf((float)(end - beg), 1.f);
            uint4 pk = finalize_node(sums, invd, selfh_in, gamma, beta, mean, var,
                                     (size_t)node, 8 * sl);
            *reinterpret_cast<uint4*>(&As[nl * LDA + 8 * sl]) = pk;
        }
    }
    __syncthreads();

    float acc[16][4];
#pragma unroll
    for (int nt = 0; nt < 16; nt++)
#pragma unroll
        for (int q = 0; q < 4; q++) acc[nt][q] = 0.f;

    const uint32_t a_base = smem_u32(
        &As[(warp * 16 + (lane & 15)) * LDA + ((lane >> 4) << 3)]);
    const int grp = lane >> 3;
    const uint32_t b_base = smem_u32(
        &Ws[(((grp >> 1) << 3) + (lane & 7)) * LDA + ((grp & 1) << 3)]);
    constexpr uint32_t B_P_STRIDE = 16 * LDA * 2;

#pragma unroll
    for (int kb = 0; kb < 64; kb += 16) {
        uint32_t a0, a1, a2, a3;
        asm volatile("ldmatrix.sync.aligned.m8n8.x4.shared.b16 {%0,%1,%2,%3}, [%4];"
                     : "=r"(a0), "=r"(a1), "=r"(a2), "=r"(a3)
                     : "r"(a_base + kb * 2));
#pragma unroll
        for (int p = 0; p < 8; p++) {
            uint32_t b0, b1, b2, b3;
            asm volatile("ldmatrix.sync.aligned.m8n8.x4.shared.b16 {%0,%1,%2,%3}, [%4];"
                         : "=r"(b0), "=r"(b1), "=r"(b2), "=r"(b3)
                         : "r"(b_base + p * B_P_STRIDE + kb * 2));
            asm volatile(
                "mma.sync.aligned.m16n8k16.row.col.f32.f16.f16.f32 "
                "{%0,%1,%2,%3}, {%4,%5,%6,%7}, {%8,%9}, {%0,%1,%2,%3};"
                : "+f"(acc[2 * p][0]), "+f"(acc[2 * p][1]),
                  "+f"(acc[2 * p][2]), "+f"(acc[2 * p][3])
                : "r"(a0), "r"(a1), "r"(a2), "r"(a3), "r"(b0), "r"(b1));
            asm volatile(
                "mma.sync.aligned.m16n8k16.row.col.f32.f16.f16.f32 "
                "{%0,%1,%2,%3}, {%4,%5,%6,%7}, {%8,%9}, {%0,%1,%2,%3};"
                : "+f"(acc[2 * p + 1][0]), "+f"(acc[2 * p + 1][1]),
                  "+f"(acc[2 * p + 1][2]), "+f"(acc[2 * p + 1][3])
                : "r"(a0), "r"(a1), "r"(a2), "r"(a3), "r"(b2), "r"(b3));
        }
    }

    const int r0 = n0 + warp * 16 + g;
    const int r1 = r0 + 8;
#pragma unroll
    for (int nt = 0; nt < 8; nt++) {
        int col = nt * 8 + tg * 2;
        if (r0 < N) {
            __half2 h = __floats2half2_rn(acc[nt][0], acc[nt][1]);
            *reinterpret_cast<__half2*>(Yh_out + (size_t)r0 * 64 + col) = h;
        }
        if (r1 < N) {
            __half2 h = __floats2half2_rn(acc[nt][2], acc[nt][3]);
            *reinterpret_cast<__half2*>(Yh_out + (size_t)r1 * 64 + col) = h;
        }
    }
#pragma unroll
    for (int nt = 8; nt < 16; nt++) {
        int col = (nt - 8) * 8 + tg * 2;
        float bx = bls[col], by = bls[col + 1];
        if (r0 < N) {
            __half2 h = __floats2half2_rn(acc[nt][0] + bx, acc[nt][1] + by);
            *reinterpret_cast<__half2*>(selfh_out + (size_t)r0 * 64 + col) = h;
        }
        if (r1 < N) {
            __half2 h = __floats2half2_rn(acc[nt][2] + bx, acc[nt][3] + by);
            *reinterpret_cast<__half2*>(selfh_out + (size_t)r1 * 64 + col) = h;
        }
    }
}

// ---------------------------------------------------------------------------
// fused head: agg(layer 2) -> smem h tile -> head MLP -> out
// ---------------------------------------------------------------------------
__global__ __launch_bounds__(256, 2)
void fused_head(const int* __restrict__ rowptr, const int* __restrict__ csrc,
                const __half* __restrict__ Yh_in, const __half* __restrict__ selfh_in,
                const float* __restrict__ gamma, const float* __restrict__ beta,
                const float* __restrict__ mean, const float* __restrict__ var,
                const float* __restrict__ W1, const float* __restrict__ b1,
                const float* __restrict__ W2, const float* __restrict__ b2,
                float* __restrict__ out, int N) {
    constexpr int LDA = 72;
    extern __shared__ __half sm[];
    __half* As = sm;                                 // [128][72]
    float* w1t = (float*)(sm + 128 * LDA);           // [64][32]
    float* b1s = w1t + 64 * 32;
    float* w2s = b1s + 32;
    float* b2s = w2s + 32;

    const int t = threadIdx.x;
    const int warp = t >> 5, lane = t & 31;
    const int n0 = blockIdx.x * 128;
    const int sl = t & 7;
    const unsigned smask = 0xffu << (t & 24);

    for (int idx = t; idx < 64 * 32; idx += 256) {
        int k = idx >> 5, o = idx & 31;
        w1t[idx] = W1[o * 64 + k];
    }
    if (t < 32) { b1s[t] = b1[t]; w2s[t] = W2[t]; }
    if (t == 0) b2s[0] = b2[0];

    const uint4* Y4 = reinterpret_cast<const uint4*>(Yh_in);
#pragma unroll
    for (int r = 0; r < 4; r++) {
        int nl = r * 32 + (t >> 3);
        int node = n0 + nl;
        if (node < N) {
            int beg = rowptr[node], end = rowptr[node + 1];
            float sums[8];
            gather_node(Y4, csrc, beg, end, sl, smask, sums);
            float invd = 1.f / fmaxf((float)(end - beg), 1.f);
            uint4 pk = finalize_node(sums, invd, selfh_in, gamma, beta, mean, var,
                                     (size_t)node, 8 * sl);
            *reinterpret_cast<uint4*>(&As[nl * LDA + 8 * sl]) = pk;
        }
    }
    __syncthreads();

    for (int r = 0; r < 16; r++) {
        int nl = r * 8 + warp;
        int n = n0 + nl;
        if (n >= N) continue;
        __half2 raw = *reinterpret_cast<const __half2*>(&As[nl * LDA + lane * 2]);
        float2 hv = __half22float2(raw);
        float acc = 0.f;
#pragma unroll
        for (int q = 0; q < 32; q++) {
            float h0 = __shfl_sync(0xffffffffu, hv.x, q);
            float h1 = __shfl_sync(0xffffffffu, hv.y, q);
            acc += h0 * w1t[(2 * q) * 32 + lane];
            acc += h1 * w1t[(2 * q + 1) * 32 + lane];
        }
        float p = fmaxf(acc + b1s[lane], 0.f) * w2s[lane];
#pragma unroll
        for (int off = 16; off > 0; off >>= 1)
            p += __shfl_down_sync(0xffffffffu, p, off);
        if (lane == 0) out[n] = p + b2s[0];
    }
}

// ---------------------------------------------------------------------------
extern "C" void kernel_launch(void* const* d_in, const int* in_sizes, int n_in,
                              void* d_out, int out_size) {
    const float* x   = (const float*)d_in[0];
    const int*   ei  = (const int*)d_in[1];
    const float* Wl0 = (const float*)d_in[2];
    const float* Wr0 = (const float*)d_in[3];
    const float* bl0 = (const float*)d_in[4];
    const float* Wl1 = (const float*)d_in[5];
    const float* Wr1 = (const float*)d_in[6];
    const float* bl1 = (const float*)d_in[7];
    const float* Wl2 = (const float*)d_in[8];
    const float* Wr2 = (const float*)d_in[9];
    const float* bl2 = (const float*)d_in[10];
    const float* bng = (const float*)d_in[11];
    const float* bnb = (const float*)d_in[12];
    const float* bnm = (const float*)d_in[13];
    const float* bnv = (const float*)d_in[14];
    const float* hW1 = (const float*)d_in[15];
    const float* hb1 = (const float*)d_in[16];
    const float* hW2 = (const float*)d_in[17];
    const float* hb2 = (const float*)d_in[18];

    const int N = in_sizes[0] / 128;
    const int E = in_sizes[1] / 2;
    const int* src = ei;
    const int* dst = ei + E;

    __half *yhA, *selfhA, *yhB, *selfhB, *w0, *w1, *w2;
    int *deg, *rowptr, *cursor, *csrc;
    unsigned* state;
    cudaGetSymbolAddress((void**)&yhA,    g_yhA);
    cudaGetSymbolAddress((void**)&selfhA, g_selfhA);
    cudaGetSymbolAddress((void**)&yhB,    g_yhB);
    cudaGetSymbolAddress((void**)&selfhB, g_selfhB);
    cudaGetSymbolAddress((void**)&deg,    g_deg);
    cudaGetSymbolAddress((void**)&rowptr, g_rowptr);
    cudaGetSymbolAddress((void**)&cursor, g_cursor);
    cudaGetSymbolAddress((void**)&csrc,   g_csrc);
    cudaGetSymbolAddress((void**)&state,  g_state);
    cudaGetSymbolAddress((void**)&w0,     g_w0);
    cudaGetSymbolAddress((void**)&w1,     g_w1);
    cudaGetSymbolAddress((void**)&w2,     g_w2);

    const int SMEM_CS128 = 192 * (128 + 8) * 2 + 256;         // 52480
    const int SMEM_FL    = 2 * 128 * 72 * 2 + 256;            // 37120
    const int SMEM_FH    = 128 * 72 * 2 + (64 * 32 + 65) * 4; // 26948
    cudaFuncSetAttribute((const void*)gemm_scatter<float, 128>,
                         cudaFuncAttributeMaxDynamicSharedMemorySize, SMEM_CS128);
    cudaFuncSetAttribute((const void*)fused_layer,
                         cudaFuncAttributeMaxDynamicSharedMemorySize, SMEM_FL);
    cudaFuncSetAttribute((const void*)fused_head,
                         cudaFuncAttributeMaxDynamicSharedMemorySize, SMEM_FH);

    const int gblocks = (N + 127) / 128;           // 782
    const dim3 ggrid(gblocks, 3);                  // y=0,1 gemm halves; y=2 scatter
    const int e4blocks = ((E + 3) / 4 + 255) / 256;
    const int nscan    = (N + 1023) / 1024;

    // #1 prep (weights + zero deg/state), #2 deg, #3 scan,
    // #4 gemm128 + scatter merged (profiled slot)
    prep_all<<<(N + 255) / 256, 256>>>(Wl0, Wr0, Wl1, Wr1, Wl2, Wr2,
                                       w0, w1, w2, deg, state, N);
    deg_kernel<<<e4blocks, 256>>>(dst, deg, E);
    scan_lookback<<<nscan, 256>>>(deg, rowptr, cursor, state, N);
    gemm_scatter<float, 128><<<ggrid, 256, SMEM_CS128>>>(
        x, w0, bl0, yhA, selfhA, N, src, dst, cursor, csrc, E);

    // fused layers: agg0+gemm1 (A->B), agg1+gemm2 (B->A), agg2+head (A->out)
    fused_layer<<<gblocks, 256, SMEM_FL>>>(rowptr, csrc, yhA, selfhA,
                                           bng, bnb, bnm, bnv,
                                           w1, bl1, yhB, selfhB, N);
    fused_layer<<<gblocks, 256, SMEM_FL>>>(rowptr, csrc, yhB, selfhB,
                                           bng + 64, bnb + 64, bnm + 64, bnv + 64,
                                           w2, bl2, yhA, selfhA, N);
    fused_head<<<gblocks, 256, SMEM_FH>>>(rowptr, csrc, yhA, selfhA,
                                          bng + 128, bnb + 128, bnm + 128, bnv + 128,
                                          hW1, hb1, hW2, hb2, (float*)d_out, N);
}

// round 16
// speedup vs baseline: 1.0746x; 1.0746x over previous
#include <cuda_runtime.h>
#include <cuda_fp16.h>
#include <cstdint>

#define MAXN 100096
#define MAXE 3200000

// ---- scratch (device globals; no allocation allowed) ----
__device__ __half g_yhA[MAXN * 64];
__device__ __half g_selfhA[MAXN * 64];
__device__ __half g_yhB[MAXN * 64];
__device__ __half g_selfhB[MAXN * 64];
__device__ int      g_deg[MAXN];
__device__ int      g_rowptr[MAXN + 1];
__device__ int      g_cursor[MAXN];
__device__ int      g_csrc[MAXE];
__device__ unsigned g_state[256];      // lookback scan tile states
__device__ __half g_w0[128 * 128];     // fused [Wl0|Wr0] fp16, row-major [o][k]
__device__ __half g_w1[128 * 64];
__device__ __half g_w2[128 * 64];

__device__ __forceinline__ uint32_t smem_u32(const void* p) {
    uint32_t a;
    asm("{ .reg .u64 t; cvta.to.shared.u64 t, %1; cvt.u32.u64 %0, t; }" : "=r"(a) : "l"(p));
    return a;
}

// ---------------------------------------------------------------------------
// prep: weight fp32->fp16 fused images + zero deg + zero scan state
// ---------------------------------------------------------------------------
__global__ void prep_all(const float* __restrict__ Wl0, const float* __restrict__ Wr0,
                         const float* __restrict__ Wl1, const float* __restrict__ Wr1,
                         const float* __restrict__ Wl2, const float* __restrict__ Wr2,
                         __half* __restrict__ w0, __half* __restrict__ w1,
                         __half* __restrict__ w2,
                         int* __restrict__ deg, unsigned* __restrict__ state, int N) {
    int i = blockIdx.x * blockDim.x + threadIdx.x;
    if (i < 128 * 128) {
        int o = i >> 7, k = i & 127;
        float v = (o < 64) ? Wl0[o * 128 + k] : Wr0[(o - 64) * 128 + k];
        w0[i] = __float2half_rn(v);
    } else if (i < 128 * 128 + 128 * 64) {
        int j = i - 128 * 128;
        int o = j >> 6, k = j & 63;
        float v = (o < 64) ? Wl1[o * 64 + k] : Wr1[(o - 64) * 64 + k];
        w1[j] = __float2half_rn(v);
    } else if (i < 128 * 128 + 2 * 128 * 64) {
        int j = i - 128 * 128 - 128 * 64;
        int o = j >> 6, k = j & 63;
        float v = (o < 64) ? Wl2[o * 64 + k] : Wr2[(o - 64) * 64 + k];
        w2[j] = __float2half_rn(v);
    }
    if (i < N) deg[i] = 0;
    if (i < 256) state[i] = 0u;
}

// ---------------------------------------------------------------------------
// degree: int4-vectorized, 4 edges per thread
// ---------------------------------------------------------------------------
__global__ void deg_kernel(const int* __restrict__ dst, int* __restrict__ deg, int E) {
    int t = blockIdx.x * blockDim.x + threadIdx.x;
    int i4 = t * 4;
    if (i4 + 3 < E) {
        int4 d = __ldg((const int4*)dst + t);
        atomicAdd(&deg[d.x], 1);
        atomicAdd(&deg[d.y], 1);
        atomicAdd(&deg[d.z], 1);
        atomicAdd(&deg[d.w], 1);
    } else {
        for (int j = i4; j < E; j++) atomicAdd(&deg[dst[j]], 1);
    }
}

// ---------------------------------------------------------------------------
// single-kernel exclusive scan via decoupled lookback
// ---------------------------------------------------------------------------
__global__ void scan_lookback(const int* __restrict__ deg, int* __restrict__ rowptr,
                              int* __restrict__ cursor, unsigned* __restrict__ state,
                              int N) {
    __shared__ int sh[256];
    __shared__ int s_excl;
    const unsigned FULL = 0xffffffffu;
    const int b = blockIdx.x, t = threadIdx.x;
    const int base = b * 1024 + t * 4;
    int v[4];
#pragma unroll
    for (int k = 0; k < 4; k++) v[k] = (base + k < N) ? deg[base + k] : 0;
    int tot = v[0] + v[1] + v[2] + v[3];
    sh[t] = tot;
    __syncthreads();
#pragma unroll
    for (int off = 1; off < 256; off <<= 1) {
        int x = (t >= off) ? sh[t - off] : 0;
        __syncthreads();
        sh[t] += x;
        __syncthreads();
    }
    const int blockTotal = sh[255];
    const int local_excl = sh[t] - tot;

    if (b == 0) {
        if (t == 0) {
            atomicExch(&state[0], (2u << 30) | (unsigned)blockTotal);
            s_excl = 0;
        }
    } else {
        if (t == 0)
            atomicExch(&state[b], (1u << 30) | (unsigned)blockTotal);
        if (t < 32) {
            int lane = t;
            int excl = 0;
            int tile = b - 1;
            while (true) {
                int widx = tile - lane;
                unsigned st;
                if (widx < 0) {
                    st = 2u << 30;
                } else {
                    do { st = atomicAdd(&state[widx], 0u); } while ((st >> 30) == 0u);
                }
                unsigned pm = __ballot_sync(FULL, (st >> 30) == 2u);
                int closest = __ffs(pm) - 1;
                int val = (int)(st & 0x3FFFFFFFu);
                int contrib;
                if (pm == 0) contrib = val;
                else contrib = (lane <= closest) ? val : 0;
#pragma unroll
                for (int off = 16; off > 0; off >>= 1)
                    contrib += __shfl_down_sync(FULL, contrib, off);
                excl += __shfl_sync(FULL, contrib, 0);
                if (pm) break;
                tile -= 32;
            }
            if (lane == 0) {
                s_excl = excl;
                atomicExch(&state[b], (2u << 30) | (unsigned)(excl + blockTotal));
            }
        }
    }
    __syncthreads();
    int run = s_excl + local_excl;
#pragma unroll
    for (int k = 0; k < 4; k++) {
        if (base + k < N) { rowptr[base + k] = run; cursor[base + k] = run; }
        run += v[k];
    }
    if (b == gridDim.x - 1 && t == 255) rowptr[N] = s_excl + blockTotal;
}

// ---------------------------------------------------------------------------
// scatter: int4-vectorized, 4 edges per thread (R14 shape: max concurrency)
// ---------------------------------------------------------------------------
__global__ void scatter_kernel(const int* __restrict__ src, const int* __restrict__ dst,
                               int* __restrict__ cursor, int* __restrict__ csrc, int E) {
    int t = blockIdx.x * blockDim.x + threadIdx.x;
    int i4 = t * 4;
    if (i4 + 3 < E) {
        int4 s = __ldg((const int4*)src + t);
        int4 d = __ldg((const int4*)dst + t);
        csrc[atomicAdd(&cursor[d.x], 1)] = s.x;
        csrc[atomicAdd(&cursor[d.y], 1)] = s.y;
        csrc[atomicAdd(&cursor[d.z], 1)] = s.z;
        csrc[atomicAdd(&cursor[d.w], 1)] = s.w;
    } else {
        for (int j = i4; j < E; j++) {
            int pos = atomicAdd(&cursor[dst[j]], 1);
            csrc[pos] = src[j];
        }
    }
}

// ---------------------------------------------------------------------------
// gather helper: 8-lane group aggregates one node's neighborhood (fp16 rows)
// ---------------------------------------------------------------------------
__device__ __forceinline__ void gather_node(
    const uint4* __restrict__ Y4, const int* __restrict__ csrc,
    int beg, int end, int sl, unsigned smask, float* sums) {
    float2 acc0 = make_float2(0.f, 0.f), acc1 = make_float2(0.f, 0.f);
    float2 acc2 = make_float2(0.f, 0.f), acc3 = make_float2(0.f, 0.f);
    int idx = (beg + sl < end) ? __ldg(csrc + beg + sl) : 0;
    for (int i = beg; i < end; i += 8) {
        int nxt = (i + 8 + sl < end) ? __ldg(csrc + i + 8 + sl) : 0;
        int cnt = min(8, end - i);
        if (cnt == 8) {
            int s[8];
#pragma unroll
            for (int u = 0; u < 8; u++) s[u] = __shfl_sync(smask, idx, u, 8);
            uint4 v[8];
#pragma unroll
            for (int u = 0; u < 8; u++) v[u] = __ldg(Y4 + (size_t)s[u] * 8 + sl);
#pragma unroll
            for (int u = 0; u < 8; u++) {
                float2 f0 = __half22float2(*reinterpret_cast<__half2*>(&v[u].x));
                float2 f1 = __half22float2(*reinterpret_cast<__half2*>(&v[u].y));
                float2 f2 = __half22float2(*reinterpret_cast<__half2*>(&v[u].z));
                float2 f3 = __half22float2(*reinterpret_cast<__half2*>(&v[u].w));
                acc0.x += f0.x; acc0.y += f0.y;
                acc1.x += f1.x; acc1.y += f1.y;
                acc2.x += f2.x; acc2.y += f2.y;
                acc3.x += f3.x; acc3.y += f3.y;
            }
        } else {
            for (int j = 0; j < cnt; j++) {
                int s0 = __shfl_sync(smask, idx, j, 8);
                uint4 v = __ldg(Y4 + (size_t)s0 * 8 + sl);
                float2 f0 = __half22float2(*reinterpret_cast<__half2*>(&v.x));
                float2 f1 = __half22float2(*reinterpret_cast<__half2*>(&v.y));
                float2 f2 = __half22float2(*reinterpret_cast<__half2*>(&v.z));
                float2 f3 = __half22float2(*reinterpret_cast<__half2*>(&v.w));
                acc0.x += f0.x; acc0.y += f0.y;
                acc1.x += f1.x; acc1.y += f1.y;
                acc2.x += f2.x; acc2.y += f2.y;
                acc3.x += f3.x; acc3.y += f3.y;
            }
        }
        idx = nxt;
    }
    sums[0] = acc0.x; sums[1] = acc0.y; sums[2] = acc1.x; sums[3] = acc1.y;
    sums[4] = acc2.x; sums[5] = acc2.y; sums[6] = acc3.x; sums[7] = acc3.y;
}

// finalize helper: mean + self + BN + ReLU -> 8 fp16 packed in uint4
__device__ __forceinline__ uint4 finalize_node(
    const float* sums, float invd, const __half* __restrict__ selfh,
    const float* __restrict__ gamma, const float* __restrict__ beta,
    const float* __restrict__ mean, const float* __restrict__ var,
    size_t node, int f) {
    uint4 sp = *reinterpret_cast<const uint4*>(selfh + node * 64 + f);
    float2 s01 = __half22float2(*reinterpret_cast<__half2*>(&sp.x));
    float2 s23 = __half22float2(*reinterpret_cast<__half2*>(&sp.y));
    float2 s45 = __half22float2(*reinterpret_cast<__half2*>(&sp.z));
    float2 s67 = __half22float2(*reinterpret_cast<__half2*>(&sp.w));
    float sva[8] = {s01.x, s01.y, s23.x, s23.y, s45.x, s45.y, s67.x, s67.y};
    float4 g0 = *reinterpret_cast<const float4*>(gamma + f);
    float4 g1 = *reinterpret_cast<const float4*>(gamma + f + 4);
    float4 b0 = *reinterpret_cast<const float4*>(beta + f);
    float4 b1 = *reinterpret_cast<const float4*>(beta + f + 4);
    float4 m0 = *reinterpret_cast<const float4*>(mean + f);
    float4 m1 = *reinterpret_cast<const float4*>(mean + f + 4);
    float4 v0 = *reinterpret_cast<const float4*>(var + f);
    float4 v1 = *reinterpret_cast<const float4*>(var + f + 4);
    float ga[8] = {g0.x, g0.y, g0.z, g0.w, g1.x, g1.y, g1.z, g1.w};
    float ba[8] = {b0.x, b0.y, b0.z, b0.w, b1.x, b1.y, b1.z, b1.w};
    float ma[8] = {m0.x, m0.y, m0.z, m0.w, m1.x, m1.y, m1.z, m1.w};
    float va[8] = {v0.x, v0.y, v0.z, v0.w, v1.x, v1.y, v1.z, v1.w};
    float o[8];
#pragma unroll
    for (int k = 0; k < 8; k++)
        o[k] = fmaxf((sums[k] * invd + sva[k] - ma[k]) * rsqrtf(va[k] + 1e-5f) * ga[k] + ba[k], 0.f);
    __half2 p0 = __floats2half2_rn(o[0], o[1]);
    __half2 p1 = __floats2half2_rn(o[2], o[3]);
    __half2 p2 = __floats2half2_rn(o[4], o[5]);
    __half2 p3 = __floats2half2_rn(o[6], o[7]);
    uint4 pk;
    pk.x = *reinterpret_cast<uint32_t*>(&p0);
    pk.y = *reinterpret_cast<uint32_t*>(&p1);
    pk.z = *reinterpret_cast<uint32_t*>(&p2);
    pk.w = *reinterpret_cast<uint32_t*>(&p3);
    return pk;
}

// ---------------------------------------------------------------------------
// layer-0 GEMM: column-split HMMA + ldmatrix; 4 CTAs/SM (R14, 34 µs)
// ---------------------------------------------------------------------------
template <typename T, int KIN>
__global__ __launch_bounds__(256, 4)
void gemm_cs(const T* __restrict__ X, const __half* __restrict__ Wimg,
             const float* __restrict__ blv,
             __half* __restrict__ Yh, __half* __restrict__ Sh, int N) {
    constexpr int LDA = KIN + 8;
    extern __shared__ __half sm[];
    __half* As = sm;
    __half* Ws = sm + 128 * LDA;
    float* bls = (float*)(sm + 192 * LDA);

    const int t = threadIdx.x;
    const int warp = t >> 5, lane = t & 31;
    const int g = lane >> 2, tg = lane & 3;
    const int n0 = blockIdx.x * 128;
    const int half_sel = blockIdx.y;

    if (t < 64) bls[t] = blv[t];

    {
        const __half* wsrc = Wimg + (size_t)half_sel * 64 * KIN;
        constexpr int NW = 64 * KIN / 8;
        for (int c = t; c < NW; c += 256) {
            int row = c / (KIN / 8);
            int k = (c % (KIN / 8)) * 8;
            *(uint4*)&Ws[row * LDA + k] = *(const uint4*)&wsrc[row * KIN + k];
        }
    }
    {
        constexpr int NA = 128 * KIN / 8;
        for (int c = t; c < NA; c += 256) {
            int row = c / (KIN / 8);
            int k = (c % (KIN / 8)) * 8;
            int n = n0 + row;
            uint4 hv = make_uint4(0u, 0u, 0u, 0u);
            if (n < N) {
                if constexpr (sizeof(T) == 4) {
                    const float4* xp = (const float4*)(X + (size_t)n * KIN + k);
                    float4 v0 = xp[0], v1 = xp[1];
                    __half2 h0 = __floats2half2_rn(v0.x, v0.y);
                    __half2 h1 = __floats2half2_rn(v0.z, v0.w);
                    __half2 h2 = __floats2half2_rn(v1.x, v1.y);
                    __half2 h3 = __floats2half2_rn(v1.z, v1.w);
                    hv.x = *reinterpret_cast<uint32_t*>(&h0);
                    hv.y = *reinterpret_cast<uint32_t*>(&h1);
                    hv.z = *reinterpret_cast<uint32_t*>(&h2);
                    hv.w = *reinterpret_cast<uint32_t*>(&h3);
                } else {
                    hv = *(const uint4*)&X[(size_t)n * KIN + k];
                }
            }
            *(uint4*)&As[row * LDA + k] = hv;
        }
    }
    __syncthreads();

    float acc[8][4];
#pragma unroll
    for (int nt = 0; nt < 8; nt++)
#pragma unroll
        for (int q = 0; q < 4; q++) acc[nt][q] = 0.f;

    const uint32_t a_base = smem_u32(
        &As[(warp * 16 + (lane & 15)) * LDA + ((lane >> 4) << 3)]);
    const int grp = lane >> 3;
    const uint32_t b_base = smem_u32(
        &Ws[(((grp >> 1) << 3) + (lane & 7)) * LDA + ((grp & 1) << 3)]);
    constexpr uint32_t B_P_STRIDE = 16 * LDA * 2;

#pragma unroll
    for (int kb = 0; kb < KIN; kb += 16) {
        uint32_t a0, a1, a2, a3;
        asm volatile("ldmatrix.sync.aligned.m8n8.x4.shared.b16 {%0,%1,%2,%3}, [%4];"
                     : "=r"(a0), "=r"(a1), "=r"(a2), "=r"(a3)
                     : "r"(a_base + kb * 2));
#pragma unroll
        for (int p = 0; p < 4; p++) {
            uint32_t b0, b1, b2, b3;
            asm volatile("ldmatrix.sync.aligned.m8n8.x4.shared.b16 {%0,%1,%2,%3}, [%4];"
                         : "=r"(b0), "=r"(b1), "=r"(b2), "=r"(b3)
                         : "r"(b_base + p * B_P_STRIDE + kb * 2));
            asm volatile(
                "mma.sync.aligned.m16n8k16.row.col.f32.f16.f16.f32 "
                "{%0,%1,%2,%3}, {%4,%5,%6,%7}, {%8,%9}, {%0,%1,%2,%3};"
                : "+f"(acc[2 * p][0]), "+f"(acc[2 * p][1]),
                  "+f"(acc[2 * p][2]), "+f"(acc[2 * p][3])
                : "r"(a0), "r"(a1), "r"(a2), "r"(a3), "r"(b0), "r"(b1));
            asm volatile(
                "mma.sync.aligned.m16n8k16.row.col.f32.f16.f16.f32 "
                "{%0,%1,%2,%3}, {%4,%5,%6,%7}, {%8,%9}, {%0,%1,%2,%3};"
                : "+f"(acc[2 * p + 1][0]), "+f"(acc[2 * p + 1][1]),
                  "+f"(acc[2 * p + 1][2]), "+f"(acc[2 * p + 1][3])
                : "r"(a0), "r"(a1), "r"(a2), "r"(a3), "r"(b2), "r"(b3));
        }
    }

    const int r0 = n0 + warp * 16 + g;
    const int r1 = r0 + 8;
    if (half_sel == 0) {
#pragma unroll
        for (int nt = 0; nt < 8; nt++) {
            int col = nt * 8 + tg * 2;
            if (r0 < N) {
                __half2 h = __floats2half2_rn(acc[nt][0], acc[nt][1]);
                *reinterpret_cast<__half2*>(Yh + (size_t)r0 * 64 + col) = h;
            }
            if (r1 < N) {
                __half2 h = __floats2half2_rn(acc[nt][2], acc[nt][3]);
                *reinterpret_cast<__half2*>(Yh + (size_t)r1 * 64 + col) = h;
            }
        }
    } else {
#pragma unroll
        for (int nt = 0; nt < 8; nt++) {
            int col = nt * 8 + tg * 2;
            float bx = bls[col], by = bls[col + 1];
            if (r0 < N) {
                __half2 h = __floats2half2_rn(acc[nt][0] + bx, acc[nt][1] + by);
                *reinterpret_cast<__half2*>(Sh + (size_t)r0 * 64 + col) = h;
            }
            if (r1 < N) {
                __half2 h = __floats2half2_rn(acc[nt][2] + bx, acc[nt][3] + by);
                *reinterpret_cast<__half2*>(Sh + (size_t)r1 * 64 + col) = h;
            }
        }
    }
}

// ---------------------------------------------------------------------------
// fused layer: agg(layer i) -> smem h tile -> HMMA (layer i+1, full 128 cols)
// ---------------------------------------------------------------------------
__global__ __launch_bounds__(256, 2)
void fused_layer(const int* __restrict__ rowptr, const int* __restrict__ csrc,
                 const __half* __restrict__ Yh_in, const __half* __restrict__ selfh_in,
                 const float* __restrict__ gamma, const float* __restrict__ beta,
                 const float* __restrict__ mean, const float* __restrict__ var,
                 const __half* __restrict__ Wimg, const float* __restrict__ blv,
                 __half* __restrict__ Yh_out, __half* __restrict__ selfh_out, int N) {
    constexpr int LDA = 72;
    extern __shared__ __half sm[];
    __half* As = sm;                            // [128][72] h tile
    __half* Ws = sm + 128 * LDA;                // [128][72] weights
    float* bls = (float*)(sm + 2 * 128 * LDA);  // [64]

    const int t = threadIdx.x;
    const int warp = t >> 5, lane = t & 31;
    const int g = lane >> 2, tg = lane & 3;
    const int n0 = blockIdx.x * 128;
    const int sl = t & 7;
    const unsigned smask = 0xffu << (t & 24);

    if (t < 64) bls[t] = blv[t];
    for (int c = t; c < 1024; c += 256) {
        int row = c >> 3, k = (c & 7) * 8;
        *(uint4*)&Ws[row * LDA + k] = *(const uint4*)&Wimg[row * 64 + k];
    }

    const uint4* Y4 = reinterpret_cast<const uint4*>(Yh_in);
#pragma unroll
    for (int r = 0; r < 4; r++) {
        int nl = r * 32 + (t >> 3);
        int node = n0 + nl;
        if (node < N) {
            int beg = rowptr[node], end = rowptr[node + 1];
            float sums[8];
            gather_node(Y4, csrc, beg, end, sl, smask, sums);
            float invd = 1.f / fmaxf((float)(end - beg), 1.f);
            uint4 pk = finalize_node(sums, invd, selfh_in, gamma, beta, mean, var,
                                     (size_t)node, 8 * sl);
            *reinterpret_cast<uint4*>(&As[nl * LDA + 8 * sl]) = pk;
        }
    }
    __syncthreads();

    float acc[16][4];
#pragma unroll
    for (int nt = 0; nt < 16; nt++)
#pragma unroll
        for (int q = 0; q < 4; q++) acc[nt][q] = 0.f;

    const uint32_t a_base = smem_u32(
        &As[(warp * 16 + (lane & 15)) * LDA + ((lane >> 4) << 3)]);
    const int grp = lane >> 3;
    const uint32_t b_base = smem_u32(
        &Ws[(((grp >> 1) << 3) + (lane & 7)) * LDA + ((grp & 1) << 3)]);
    constexpr uint32_t B_P_STRIDE = 16 * LDA * 2;

#pragma unroll
    for (int kb = 0; kb < 64; kb += 16) {
        uint32_t a0, a1, a2, a3;
        asm volatile("ldmatrix.sync.aligned.m8n8.x4.shared.b16 {%0,%1,%2,%3}, [%4];"
                     : "=r"(a0), "=r"(a1), "=r"(a2), "=r"(a3)
                     : "r"(a_base + kb * 2));
#pragma unroll
        for (int p = 0; p < 8; p++) {
            uint32_t b0, b1, b2, b3;
            asm volatile("ldmatrix.sync.aligned.m8n8.x4.shared.b16 {%0,%1,%2,%3}, [%4];"
                         : "=r"(b0), "=r"(b1), "=r"(b2), "=r"(b3)
                         : "r"(b_base + p * B_P_STRIDE + kb * 2));
            asm volatile(
                "mma.sync.aligned.m16n8k16.row.col.f32.f16.f16.f32 "
                "{%0,%1,%2,%3}, {%4,%5,%6,%7}, {%8,%9}, {%0,%1,%2,%3};"
                : "+f"(acc[2 * p][0]), "+f"(acc[2 * p][1]),
                  "+f"(acc[2 * p][2]), "+f"(acc[2 * p][3])
                : "r"(a0), "r"(a1), "r"(a2), "r"(a3), "r"(b0), "r"(b1));
            asm volatile(
                "mma.sync.aligned.m16n8k16.row.col.f32.f16.f16.f32 "
                "{%0,%1,%2,%3}, {%4,%5,%6,%7}, {%8,%9}, {%0,%1,%2,%3};"
                : "+f"(acc[2 * p + 1][0]), "+f"(acc[2 * p + 1][1]),
                  "+f"(acc[2 * p + 1][2]), "+f"(acc[2 * p + 1][3])
                : "r"(a0), "r"(a1), "r"(a2), "r"(a3), "r"(b2), "r"(b3));
        }
    }

    const int r0 = n0 + warp * 16 + g;
    const int r1 = r0 + 8;
#pragma unroll
    for (int nt = 0; nt < 8; nt++) {
        int col = nt * 8 + tg * 2;
        if (r0 < N) {
            __half2 h = __floats2half2_rn(acc[nt][0], acc[nt][1]);
            *reinterpret_cast<__half2*>(Yh_out + (size_t)r0 * 64 + col) = h;
        }
        if (r1 < N) {
            __half2 h = __floats2half2_rn(acc[nt][2], acc[nt][3]);
            *reinterpret_cast<__half2*>(Yh_out + (size_t)r1 * 64 + col) = h;
        }
    }
#pragma unroll
    for (int nt = 8; nt < 16; nt++) {
        int col = (nt - 8) * 8 + tg * 2;
        float bx = bls[col], by = bls[col + 1];
        if (r0 < N) {
            __half2 h = __floats2half2_rn(acc[nt][0] + bx, acc[nt][1] + by);
            *reinterpret_cast<__half2*>(selfh_out + (size_t)r0 * 64 + col) = h;
        }
        if (r1 < N) {
            __half2 h = __floats2half2_rn(acc[nt][2] + bx, acc[nt][3] + by);
            *reinterpret_cast<__half2*>(selfh_out + (size_t)r1 * 64 + col) = h;
        }
    }
}

// ---------------------------------------------------------------------------
// fused head: agg(layer 2) -> smem h tile -> head MLP -> out  (4 CTAs/SM)
// ---------------------------------------------------------------------------
__global__ __launch_bounds__(256, 4)
void fused_head(const int* __restrict__ rowptr, const int* __restrict__ csrc,
                const __half* __restrict__ Yh_in, const __half* __restrict__ selfh_in,
                const float* __restrict__ gamma, const float* __restrict__ beta,
                const float* __restrict__ mean, const float* __restrict__ var,
                const float* __restrict__ W1, const float* __restrict__ b1,
                const float* __restrict__ W2, const float* __restrict__ b2,
                float* __restrict__ out, int N) {
    constexpr int LDA = 72;
    extern __shared__ __half sm[];
    __half* As = sm;                                 // [128][72]
    float* w1t = (float*)(sm + 128 * LDA);           // [64][32]
    float* b1s = w1t + 64 * 32;
    float* w2s = b1s + 32;
    float* b2s = w2s + 32;

    const int t = threadIdx.x;
    const int warp = t >> 5, lane = t & 31;
    const int n0 = blockIdx.x * 128;
    const int sl = t & 7;
    const unsigned smask = 0xffu << (t & 24);

    for (int idx = t; idx < 64 * 32; idx += 256) {
        int k = idx >> 5, o = idx & 31;
        w1t[idx] = W1[o * 64 + k];
    }
    if (t < 32) { b1s[t] = b1[t]; w2s[t] = W2[t]; }
    if (t == 0) b2s[0] = b2[0];

    const uint4* Y4 = reinterpret_cast<const uint4*>(Yh_in);
#pragma unroll
    for (int r = 0; r < 4; r++) {
        int nl = r * 32 + (t >> 3);
        int node = n0 + nl;
        if (node < N) {
            int beg = rowptr[node], end = rowptr[node + 1];
            float sums[8];
            gather_node(Y4, csrc, beg, end, sl, smask, sums);
            float invd = 1.f / fmaxf((float)(end - beg), 1.f);
            uint4 pk = finalize_node(sums, invd, selfh_in, gamma, beta, mean, var,
                                     (size_t)node, 8 * sl);
            *reinterpret_cast<uint4*>(&As[nl * LDA + 8 * sl]) = pk;
        }
    }
    __syncthreads();

    for (int r = 0; r < 16; r++) {
        int nl = r * 8 + warp;
        int n = n0 + nl;
        if (n >= N) continue;
        __half2 raw = *reinterpret_cast<const __half2*>(&As[nl * LDA + lane * 2]);
        float2 hv = __half22float2(raw);
        float acc = 0.f;
#pragma unroll
        for (int q = 0; q < 32; q++) {
            float h0 = __shfl_sync(0xffffffffu, hv.x, q);
            float h1 = __shfl_sync(0xffffffffu, hv.y, q);
            acc += h0 * w1t[(2 * q) * 32 + lane];
            acc += h1 * w1t[(2 * q + 1) * 32 + lane];
        }
        float p = fmaxf(acc + b1s[lane], 0.f) * w2s[lane];
#pragma unroll
        for (int off = 16; off > 0; off >>= 1)
            p += __shfl_down_sync(0xffffffffu, p, off);
        if (lane == 0) out[n] = p + b2s[0];
    }
}

// ---------------------------------------------------------------------------
extern "C" void kernel_launch(void* const* d_in, const int* in_sizes, int n_in,
                              void* d_out, int out_size) {
    const float* x   = (const float*)d_in[0];
    const int*   ei  = (const int*)d_in[1];
    const float* Wl0 = (const float*)d_in[2];
    const float* Wr0 = (const float*)d_in[3];
    const float* bl0 = (const float*)d_in[4];
    const float* Wl1 = (const float*)d_in[5];
    const float* Wr1 = (const float*)d_in[6];
    const float* bl1 = (const float*)d_in[7];
    const float* Wl2 = (const float*)d_in[8];
    const float* Wr2 = (const float*)d_in[9];
    const float* bl2 = (const float*)d_in[10];
    const float* bng = (const float*)d_in[11];
    const float* bnb = (const float*)d_in[12];
    const float* bnm = (const float*)d_in[13];
    const float* bnv = (const float*)d_in[14];
    const float* hW1 = (const float*)d_in[15];
    const float* hb1 = (const float*)d_in[16];
    const float* hW2 = (const float*)d_in[17];
    const float* hb2 = (const float*)d_in[18];

    const int N = in_sizes[0] / 128;
    const int E = in_sizes[1] / 2;
    const int* src = ei;
    const int* dst = ei + E;

    __half *yhA, *selfhA, *yhB, *selfhB, *w0, *w1, *w2;
    int *deg, *rowptr, *cursor, *csrc;
    unsigned* state;
    cudaGetSymbolAddress((void**)&yhA,    g_yhA);
    cudaGetSymbolAddress((void**)&selfhA, g_selfhA);
    cudaGetSymbolAddress((void**)&yhB,    g_yhB);
    cudaGetSymbolAddress((void**)&selfhB, g_selfhB);
    cudaGetSymbolAddress((void**)&deg,    g_deg);
    cudaGetSymbolAddress((void**)&rowptr, g_rowptr);
    cudaGetSymbolAddress((void**)&cursor, g_cursor);
    cudaGetSymbolAddress((void**)&csrc,   g_csrc);
    cudaGetSymbolAddress((void**)&state,  g_state);
    cudaGetSymbolAddress((void**)&w0,     g_w0);
    cudaGetSymbolAddress((void**)&w1,     g_w1);
    cudaGetSymbolAddress((void**)&w2,     g_w2);

    const int SMEM_CS128 = 192 * (128 + 8) * 2 + 256;         // 52480
    const int SMEM_FL    = 2 * 128 * 72 * 2 + 256;            // 37120
    const int SMEM_FH    = 128 * 72 * 2 + (64 * 32 + 65) * 4; // 26948
    cudaFuncSetAttribute((const void*)gemm_cs<float, 128>,
                         cudaFuncAttributeMaxDynamicSharedMemorySize, SMEM_CS128);
    cudaFuncSetAttribute((const void*)fused_layer,
                         cudaFuncAttributeMaxDynamicSharedMemorySize, SMEM_FL);
    cudaFuncSetAttribute((const void*)fused_head,
                         cudaFuncAttributeMaxDynamicSharedMemorySize, SMEM_FH);

    const int gblocks = (N + 127) / 128;
    const dim3 ggrid(gblocks, 2);
    const int e4blocks = ((E + 3) / 4 + 255) / 256;
    const int nscan    = (N + 1023) / 1024;

    // #1 prep (weights + zero deg/state), #2 deg, #3 scan, #4 gemm128 (profiled)
    prep_all<<<(N + 255) / 256, 256>>>(Wl0, Wr0, Wl1, Wr1, Wl2, Wr2,
                                       w0, w1, w2, deg, state, N);
    deg_kernel<<<e4blocks, 256>>>(dst, deg, E);
    scan_lookback<<<nscan, 256>>>(deg, rowptr, cursor, state, N);
    gemm_cs<float, 128><<<ggrid, 256, SMEM_CS128>>>(x, w0, bl0, yhA, selfhA, N);
    scatter_kernel<<<e4blocks, 256>>>(src, dst, cursor, csrc, E);

    // fused layers: agg0+gemm1 (A->B), agg1+gemm2 (B->A), agg2+head (A->out)
    fused_layer<<<gblocks, 256, SMEM_FL>>>(rowptr, csrc, yhA, selfhA,
                                           bng, bnb, bnm, bnv,
                                           w1, bl1, yhB, selfhB, N);
    fused_layer<<<gblocks, 256, SMEM_FL>>>(rowptr, csrc, yhB, selfhB,
                                           bng + 64, bnb + 64, bnm + 64, bnv + 64,
                                           w2, bl2, yhA, selfhA, N);
    fused_head<<<gblocks, 256, SMEM_FH>>>(rowptr, csrc, yhA, selfhA,
                                          bng + 128, bnb + 128, bnm + 128, bnv + 128,
                                          hW1, hb1, hW2, hb2, (float*)d_out, N);
}

// round 17
// speedup vs baseline: 1.0782x; 1.0033x over previous
#include <cuda_runtime.h>
#include <cuda_fp16.h>
#include <cstdint>

#define MAXN 100096
#define MAXE 3200000

// ---- scratch (device globals; zero-initialized at module load).
// Invariant: g_deg and g_state are ZERO at entry to every kernel_launch call;
// scan_lookback re-zeros deg after consuming it, gemm_cs re-zeros state. ----
__device__ __half g_yhA[MAXN * 64];
__device__ __half g_selfhA[MAXN * 64];
__device__ __half g_yhB[MAXN * 64];
__device__ __half g_selfhB[MAXN * 64];
__device__ int      g_deg[MAXN];
__device__ int      g_rowptr[MAXN + 1];
__device__ int      g_cursor[MAXN];
__device__ int      g_csrc[MAXE];
__device__ unsigned g_state[256];      // lookback scan tile states
__device__ __half g_w0[128 * 128];     // fused [Wl0|Wr0] fp16, row-major [o][k]
__device__ __half g_w1[128 * 64];
__device__ __half g_w2[128 * 64];

__device__ __forceinline__ uint32_t smem_u32(const void* p) {
    uint32_t a;
    asm("{ .reg .u64 t; cvta.to.shared.u64 t, %1; cvt.u32.u64 %0, t; }" : "=r"(a) : "l"(p));
    return a;
}

// ---------------------------------------------------------------------------
// prep_deg: weight fp32->fp16 fused images AND degree count (deg is zero on
// entry by the zero-invariant). Grid sized for E/4 edge chunks.
// ---------------------------------------------------------------------------
__global__ void prep_deg(const float* __restrict__ Wl0, const float* __restrict__ Wr0,
                         const float* __restrict__ Wl1, const float* __restrict__ Wr1,
                         const float* __restrict__ Wl2, const float* __restrict__ Wr2,
                         __half* __restrict__ w0, __half* __restrict__ w1,
                         __half* __restrict__ w2,
                         const int* __restrict__ dst, int* __restrict__ deg, int E) {
    int i = blockIdx.x * blockDim.x + threadIdx.x;
    // weights
    if (i < 128 * 128) {
        int o = i >> 7, k = i & 127;
        float v = (o < 64) ? Wl0[o * 128 + k] : Wr0[(o - 64) * 128 + k];
        w0[i] = __float2half_rn(v);
    } else if (i < 128 * 128 + 128 * 64) {
        int j = i - 128 * 128;
        int o = j >> 6, k = j & 63;
        float v = (o < 64) ? Wl1[o * 64 + k] : Wr1[(o - 64) * 64 + k];
        w1[j] = __float2half_rn(v);
    } else if (i < 128 * 128 + 2 * 128 * 64) {
        int j = i - 128 * 128 - 128 * 64;
        int o = j >> 6, k = j & 63;
        float v = (o < 64) ? Wl2[o * 64 + k] : Wr2[(o - 64) * 64 + k];
        w2[j] = __float2half_rn(v);
    }
    // degree (int4-vectorized)
    int i4 = i * 4;
    if (i4 + 3 < E) {
        int4 d = __ldg((const int4*)dst + i);
        atomicAdd(&deg[d.x], 1);
        atomicAdd(&deg[d.y], 1);
        atomicAdd(&deg[d.z], 1);
        atomicAdd(&deg[d.w], 1);
    } else if (i4 < E) {
        for (int j = i4; j < E; j++) atomicAdd(&deg[dst[j]], 1);
    }
}

// ---------------------------------------------------------------------------
// single-kernel exclusive scan via decoupled lookback.
// Re-zeros deg after consuming it (restores zero-invariant for next replay).
// ---------------------------------------------------------------------------
__global__ void scan_lookback(int* __restrict__ deg, int* __restrict__ rowptr,
                              int* __restrict__ cursor, unsigned* __restrict__ state,
                              int N) {
    __shared__ int sh[256];
    __shared__ int s_excl;
    const unsigned FULL = 0xffffffffu;
    const int b = blockIdx.x, t = threadIdx.x;
    const int base = b * 1024 + t * 4;
    int v[4];
#pragma unroll
    for (int k = 0; k < 4; k++) {
        v[k] = (base + k < N) ? deg[base + k] : 0;
        if (base + k < N) deg[base + k] = 0;     // restore zero-invariant
    }
    int tot = v[0] + v[1] + v[2] + v[3];
    sh[t] = tot;
    __syncthreads();
#pragma unroll
    for (int off = 1; off < 256; off <<= 1) {
        int x = (t >= off) ? sh[t - off] : 0;
        __syncthreads();
        sh[t] += x;
        __syncthreads();
    }
    const int blockTotal = sh[255];
    const int local_excl = sh[t] - tot;

    if (b == 0) {
        if (t == 0) {
            atomicExch(&state[0], (2u << 30) | (unsigned)blockTotal);
            s_excl = 0;
        }
    } else {
        if (t == 0)
            atomicExch(&state[b], (1u << 30) | (unsigned)blockTotal);
        if (t < 32) {
            int lane = t;
            int excl = 0;
            int tile = b - 1;
            while (true) {
                int widx = tile - lane;
                unsigned st;
                if (widx < 0) {
                    st = 2u << 30;
                } else {
                    do { st = atomicAdd(&state[widx], 0u); } while ((st >> 30) == 0u);
                }
                unsigned pm = __ballot_sync(FULL, (st >> 30) == 2u);
                int closest = __ffs(pm) - 1;
                int val = (int)(st & 0x3FFFFFFFu);
                int contrib;
                if (pm == 0) contrib = val;
                else contrib = (lane <= closest) ? val : 0;
#pragma unroll
                for (int off = 16; off > 0; off >>= 1)
                    contrib += __shfl_down_sync(FULL, contrib, off);
                excl += __shfl_sync(FULL, contrib, 0);
                if (pm) break;
                tile -= 32;
            }
            if (lane == 0) {
                s_excl = excl;
                atomicExch(&state[b], (2u << 30) | (unsigned)(excl + blockTotal));
            }
        }
    }
    __syncthreads();
    int run = s_excl + local_excl;
#pragma unroll
    for (int k = 0; k < 4; k++) {
        if (base + k < N) { rowptr[base + k] = run; cursor[base + k] = run; }
        run += v[k];
    }
    if (b == gridDim.x - 1 && t == 255) rowptr[N] = s_excl + blockTotal;
}

// ---------------------------------------------------------------------------
// scatter: int4-vectorized, 4 edges per thread (max concurrency)
// ---------------------------------------------------------------------------
__global__ void scatter_kernel(const int* __restrict__ src, const int* __restrict__ dst,
                               int* __restrict__ cursor, int* __restrict__ csrc, int E) {
    int t = blockIdx.x * blockDim.x + threadIdx.x;
    int i4 = t * 4;
    if (i4 + 3 < E) {
        int4 s = __ldg((const int4*)src + t);
        int4 d = __ldg((const int4*)dst + t);
        csrc[atomicAdd(&cursor[d.x], 1)] = s.x;
        csrc[atomicAdd(&cursor[d.y], 1)] = s.y;
        csrc[atomicAdd(&cursor[d.z], 1)] = s.z;
        csrc[atomicAdd(&cursor[d.w], 1)] = s.w;
    } else {
        for (int j = i4; j < E; j++) {
            int pos = atomicAdd(&cursor[dst[j]], 1);
            csrc[pos] = src[j];
        }
    }
}

// ---------------------------------------------------------------------------
// gather helper: 8-lane group aggregates one node's neighborhood (fp16 rows)
// ---------------------------------------------------------------------------
__device__ __forceinline__ void gather_node(
    const uint4* __restrict__ Y4, const int* __restrict__ csrc,
    int beg, int end, int sl, unsigned smask, float* sums) {
    float2 acc0 = make_float2(0.f, 0.f), acc1 = make_float2(0.f, 0.f);
    float2 acc2 = make_float2(0.f, 0.f), acc3 = make_float2(0.f, 0.f);
    int idx = (beg + sl < end) ? __ldg(csrc + beg + sl) : 0;
    for (int i = beg; i < end; i += 8) {
        int nxt = (i + 8 + sl < end) ? __ldg(csrc + i + 8 + sl) : 0;
        int cnt = min(8, end - i);
        if (cnt == 8) {
            int s[8];
#pragma unroll
            for (int u = 0; u < 8; u++) s[u] = __shfl_sync(smask, idx, u, 8);
            uint4 v[8];
#pragma unroll
            for (int u = 0; u < 8; u++) v[u] = __ldg(Y4 + (size_t)s[u] * 8 + sl);
#pragma unroll
            for (int u = 0; u < 8; u++) {
                float2 f0 = __half22float2(*reinterpret_cast<__half2*>(&v[u].x));
                float2 f1 = __half22float2(*reinterpret_cast<__half2*>(&v[u].y));
                float2 f2 = __half22float2(*reinterpret_cast<__half2*>(&v[u].z));
                float2 f3 = __half22float2(*reinterpret_cast<__half2*>(&v[u].w));
                acc0.x += f0.x; acc0.y += f0.y;
                acc1.x += f1.x; acc1.y += f1.y;
                acc2.x += f2.x; acc2.y += f2.y;
                acc3.x += f3.x; acc3.y += f3.y;
            }
        } else {
            for (int j = 0; j < cnt; j++) {
                int s0 = __shfl_sync(smask, idx, j, 8);
                uint4 v = __ldg(Y4 + (size_t)s0 * 8 + sl);
                float2 f0 = __half22float2(*reinterpret_cast<__half2*>(&v.x));
                float2 f1 = __half22float2(*reinterpret_cast<__half2*>(&v.y));
                float2 f2 = __half22float2(*reinterpret_cast<__half2*>(&v.z));
                float2 f3 = __half22float2(*reinterpret_cast<__half2*>(&v.w));
                acc0.x += f0.x; acc0.y += f0.y;
                acc1.x += f1.x; acc1.y += f1.y;
                acc2.x += f2.x; acc2.y += f2.y;
                acc3.x += f3.x; acc3.y += f3.y;
            }
        }
        idx = nxt;
    }
    sums[0] = acc0.x; sums[1] = acc0.y; sums[2] = acc1.x; sums[3] = acc1.y;
    sums[4] = acc2.x; sums[5] = acc2.y; sums[6] = acc3.x; sums[7] = acc3.y;
}

// finalize helper: mean + self + BN + ReLU -> 8 fp16 packed in uint4
__device__ __forceinline__ uint4 finalize_node(
    const float* sums, float invd, const __half* __restrict__ selfh,
    const float* __restrict__ gamma, const float* __restrict__ beta,
    const float* __restrict__ mean, const float* __restrict__ var,
    size_t node, int f) {
    uint4 sp = *reinterpret_cast<const uint4*>(selfh + node * 64 + f);
    float2 s01 = __half22float2(*reinterpret_cast<__half2*>(&sp.x));
    float2 s23 = __half22float2(*reinterpret_cast<__half2*>(&sp.y));
    float2 s45 = __half22float2(*reinterpret_cast<__half2*>(&sp.z));
    float2 s67 = __half22float2(*reinterpret_cast<__half2*>(&sp.w));
    float sva[8] = {s01.x, s01.y, s23.x, s23.y, s45.x, s45.y, s67.x, s67.y};
    float4 g0 = *reinterpret_cast<const float4*>(gamma + f);
    float4 g1 = *reinterpret_cast<const float4*>(gamma + f + 4);
    float4 b0 = *reinterpret_cast<const float4*>(beta + f);
    float4 b1 = *reinterpret_cast<const float4*>(beta + f + 4);
    float4 m0 = *reinterpret_cast<const float4*>(mean + f);
    float4 m1 = *reinterpret_cast<const float4*>(mean + f + 4);
    float4 v0 = *reinterpret_cast<const float4*>(var + f);
    float4 v1 = *reinterpret_cast<const float4*>(var + f + 4);
    float ga[8] = {g0.x, g0.y, g0.z, g0.w, g1.x, g1.y, g1.z, g1.w};
    float ba[8] = {b0.x, b0.y, b0.z, b0.w, b1.x, b1.y, b1.z, b1.w};
    float ma[8] = {m0.x, m0.y, m0.z, m0.w, m1.x, m1.y, m1.z, m1.w};
    float va[8] = {v0.x, v0.y, v0.z, v0.w, v1.x, v1.y, v1.z, v1.w};
    float o[8];
#pragma unroll
    for (int k = 0; k < 8; k++)
        o[k] = fmaxf((sums[k] * invd + sva[k] - ma[k]) * rsqrtf(va[k] + 1e-5f) * ga[k] + ba[k], 0.f);
    __half2 p0 = __floats2half2_rn(o[0], o[1]);
    __half2 p1 = __floats2half2_rn(o[2], o[3]);
    __half2 p2 = __floats2half2_rn(o[4], o[5]);
    __half2 p3 = __floats2half2_rn(o[6], o[7]);
    uint4 pk;
    pk.x = *reinterpret_cast<uint32_t*>(&p0);
    pk.y = *reinterpret_cast<uint32_t*>(&p1);
    pk.z = *reinterpret_cast<uint32_t*>(&p2);
    pk.w = *reinterpret_cast<uint32_t*>(&p3);
    return pk;
}

// ---------------------------------------------------------------------------
// layer-0 GEMM: column-split HMMA + ldmatrix; 4 CTAs/SM.
// Also restores state[] zero-invariant (runs after scan every replay).
// ---------------------------------------------------------------------------
template <typename T, int KIN>
__global__ __launch_bounds__(256, 4)
void gemm_cs(const T* __restrict__ X, const __half* __restrict__ Wimg,
             const float* __restrict__ blv,
             __half* __restrict__ Yh, __half* __restrict__ Sh, int N,
             unsigned* __restrict__ state) {
    constexpr int LDA = KIN + 8;
    extern __shared__ __half sm[];
    __half* As = sm;
    __half* Ws = sm + 128 * LDA;
    float* bls = (float*)(sm + 192 * LDA);

    const int t = threadIdx.x;
    const int warp = t >> 5, lane = t & 31;
    const int g = lane >> 2, tg = lane & 3;
    const int n0 = blockIdx.x * 128;
    const int half_sel = blockIdx.y;

    if (blockIdx.x == 0 && half_sel == 0 && t < 256) state[t] = 0u;  // re-zero
    if (t < 64) bls[t] = blv[t];

    {
        const __half* wsrc = Wimg + (size_t)half_sel * 64 * KIN;
        constexpr int NW = 64 * KIN / 8;
        for (int c = t; c < NW; c += 256) {
            int row = c / (KIN / 8);
            int k = (c % (KIN / 8)) * 8;
            *(uint4*)&Ws[row * LDA + k] = *(const uint4*)&wsrc[row * KIN + k];
        }
    }
    {
        constexpr int NA = 128 * KIN / 8;
        for (int c = t; c < NA; c += 256) {
            int row = c / (KIN / 8);
            int k = (c % (KIN / 8)) * 8;
            int n = n0 + row;
            uint4 hv = make_uint4(0u, 0u, 0u, 0u);
            if (n < N) {
                if constexpr (sizeof(T) == 4) {
                    const float4* xp = (const float4*)(X + (size_t)n * KIN + k);
                    float4 v0 = xp[0], v1 = xp[1];
                    __half2 h0 = __floats2half2_rn(v0.x, v0.y);
                    __half2 h1 = __floats2half2_rn(v0.z, v0.w);
                    __half2 h2 = __floats2half2_rn(v1.x, v1.y);
                    __half2 h3 = __floats2half2_rn(v1.z, v1.w);
                    hv.x = *reinterpret_cast<uint32_t*>(&h0);
                    hv.y = *reinterpret_cast<uint32_t*>(&h1);
                    hv.z = *reinterpret_cast<uint32_t*>(&h2);
                    hv.w = *reinterpret_cast<uint32_t*>(&h3);
                } else {
                    hv = *(const uint4*)&X[(size_t)n * KIN + k];
                }
            }
            *(uint4*)&As[row * LDA + k] = hv;
        }
    }
    __syncthreads();

    float acc[8][4];
#pragma unroll
    for (int nt = 0; nt < 8; nt++)
#pragma unroll
        for (int q = 0; q < 4; q++) acc[nt][q] = 0.f;

    const uint32_t a_base = smem_u32(
        &As[(warp * 16 + (lane & 15)) * LDA + ((lane >> 4) << 3)]);
    const int grp = lane >> 3;
    const uint32_t b_base = smem_u32(
        &Ws[(((grp >> 1) << 3) + (lane & 7)) * LDA + ((grp & 1) << 3)]);
    constexpr uint32_t B_P_STRIDE = 16 * LDA * 2;

#pragma unroll
    for (int kb = 0; kb < KIN; kb += 16) {
        uint32_t a0, a1, a2, a3;
        asm volatile("ldmatrix.sync.aligned.m8n8.x4.shared.b16 {%0,%1,%2,%3}, [%4];"
                     : "=r"(a0), "=r"(a1), "=r"(a2), "=r"(a3)
                     : "r"(a_base + kb * 2));
#pragma unroll
        for (int p = 0; p < 4; p++) {
            uint32_t b0, b1, b2, b3;
            asm volatile("ldmatrix.sync.aligned.m8n8.x4.shared.b16 {%0,%1,%2,%3}, [%4];"
                         : "=r"(b0), "=r"(b1), "=r"(b2), "=r"(b3)
                         : "r"(b_base + p * B_P_STRIDE + kb * 2));
            asm volatile(
                "mma.sync.aligned.m16n8k16.row.col.f32.f16.f16.f32 "
                "{%0,%1,%2,%3}, {%4,%5,%6,%7}, {%8,%9}, {%0,%1,%2,%3};"
                : "+f"(acc[2 * p][0]), "+f"(acc[2 * p][1]),
                  "+f"(acc[2 * p][2]), "+f"(acc[2 * p][3])
                : "r"(a0), "r"(a1), "r"(a2), "r"(a3), "r"(b0), "r"(b1));
            asm volatile(
                "mma.sync.aligned.m16n8k16.row.col.f32.f16.f16.f32 "
                "{%0,%1,%2,%3}, {%4,%5,%6,%7}, {%8,%9}, {%0,%1,%2,%3};"
                : "+f"(acc[2 * p + 1][0]), "+f"(acc[2 * p + 1][1]),
                  "+f"(acc[2 * p + 1][2]), "+f"(acc[2 * p + 1][3])
                : "r"(a0), "r"(a1), "r"(a2), "r"(a3), "r"(b2), "r"(b3));
        }
    }

    const int r0 = n0 + warp * 16 + g;
    const int r1 = r0 + 8;
    if (half_sel == 0) {
#pragma unroll
        for (int nt = 0; nt < 8; nt++) {
            int col = nt * 8 + tg * 2;
            if (r0 < N) {
                __half2 h = __floats2half2_rn(acc[nt][0], acc[nt][1]);
                *reinterpret_cast<__half2*>(Yh + (size_t)r0 * 64 + col) = h;
            }
            if (r1 < N) {
                __half2 h = __floats2half2_rn(acc[nt][2], acc[nt][3]);
                *reinterpret_cast<__half2*>(Yh + (size_t)r1 * 64 + col) = h;
            }
        }
    } else {
#pragma unroll
        for (int nt = 0; nt < 8; nt++) {
            int col = nt * 8 + tg * 2;
            float bx = bls[col], by = bls[col + 1];
            if (r0 < N) {
                __half2 h = __floats2half2_rn(acc[nt][0] + bx, acc[nt][1] + by);
                *reinterpret_cast<__half2*>(Sh + (size_t)r0 * 64 + col) = h;
            }
            if (r1 < N) {
                __half2 h = __floats2half2_rn(acc[nt][2] + bx, acc[nt][3] + by);
                *reinterpret_cast<__half2*>(Sh + (size_t)r1 * 64 + col) = h;
            }
        }
    }
}

// ---------------------------------------------------------------------------
// fused layer: agg(layer i) -> smem h tile -> HMMA (layer i+1, full 128 cols)
// ---------------------------------------------------------------------------
__global__ __launch_bounds__(256, 2)
void fused_layer(const int* __restrict__ rowptr, const int* __restrict__ csrc,
                 const __half* __restrict__ Yh_in, const __half* __restrict__ selfh_in,
                 const float* __restrict__ gamma, const float* __restrict__ beta,
                 const float* __restrict__ mean, const float* __restrict__ var,
                 const __half* __restrict__ Wimg, const float* __restrict__ blv,
                 __half* __restrict__ Yh_out, __half* __restrict__ selfh_out, int N) {
    constexpr int LDA = 72;
    extern __shared__ __half sm[];
    __half* As = sm;                            // [128][72] h tile
    __half* Ws = sm + 128 * LDA;                // [128][72] weights
    float* bls = (float*)(sm + 2 * 128 * LDA);  // [64]

    const int t = threadIdx.x;
    const int warp = t >> 5, lane = t & 31;
    const int g = lane >> 2, tg = lane & 3;
    const int n0 = blockIdx.x * 128;
    const int sl = t & 7;
    const unsigned smask = 0xffu << (t & 24);

    if (t < 64) bls[t] = blv[t];
    for (int c = t; c < 1024; c += 256) {
        int row = c >> 3, k = (c & 7) * 8;
        *(uint4*)&Ws[row * LDA + k] = *(const uint4*)&Wimg[row * 64 + k];
    }

    const uint4* Y4 = reinterpret_cast<const uint4*>(Yh_in);
#pragma unroll
    for (int r = 0; r < 4; r++) {
        int nl = r * 32 + (t >> 3);
        int node = n0 + nl;
        if (node < N) {
            int beg = rowptr[node], end = rowptr[node + 1];
            float sums[8];
            gather_node(Y4, csrc, beg, end, sl, smask, sums);
            float invd = 1.f / fmaxf((float)(end - beg), 1.f);
            uint4 pk = finalize_node(sums, invd, selfh_in, gamma, beta, mean, var,
                                     (size_t)node, 8 * sl);
            *reinterpret_cast<uint4*>(&As[nl * LDA + 8 * sl]) = pk;
        }
    }
    __syncthreads();

    float acc[16][4];
#pragma unroll
    for (int nt = 0; nt < 16; nt++)
#pragma unroll
        for (int q = 0; q < 4; q++) acc[nt][q] = 0.f;

    const uint32_t a_base = smem_u32(
        &As[(warp * 16 + (lane & 15)) * LDA + ((lane >> 4) << 3)]);
    const int grp = lane >> 3;
    const uint32_t b_base = smem_u32(
        &Ws[(((grp >> 1) << 3) + (lane & 7)) * LDA + ((grp & 1) << 3)]);
    constexpr uint32_t B_P_STRIDE = 16 * LDA * 2;

#pragma unroll
    for (int kb = 0; kb < 64; kb += 16) {
        uint32_t a0, a1, a2, a3;
        asm volatile("ldmatrix.sync.aligned.m8n8.x4.shared.b16 {%0,%1,%2,%3}, [%4];"
                     : "=r"(a0), "=r"(a1), "=r"(a2), "=r"(a3)
                     : "r"(a_base + kb * 2));
#pragma unroll
        for (int p = 0; p < 8; p++) {
            uint32_t b0, b1, b2, b3;
            asm volatile("ldmatrix.sync.aligned.m8n8.x4.shared.b16 {%0,%1,%2,%3}, [%4];"
                         : "=r"(b0), "=r"(b1), "=r"(b2), "=r"(b3)
                         : "r"(b_base + p * B_P_STRIDE + kb * 2));
            asm volatile(
                "mma.sync.aligned.m16n8k16.row.col.f32.f16.f16.f32 "
                "{%0,%1,%2,%3}, {%4,%5,%6,%7}, {%8,%9}, {%0,%1,%2,%3};"
                : "+f"(acc[2 * p][0]), "+f"(acc[2 * p][1]),
                  "+f"(acc[2 * p][2]), "+f"(acc[2 * p][3])
                : "r"(a0), "r"(a1), "r"(a2), "r"(a3), "r"(b0), "r"(b1));
            asm volatile(
                "mma.sync.aligned.m16n8k16.row.col.f32.f16.f16.f32 "
                "{%0,%1,%2,%3}, {%4,%5,%6,%7}, {%8,%9}, {%0,%1,%2,%3};"
                : "+f"(acc[2 * p + 1][0]), "+f"(acc[2 * p + 1][1]),
                  "+f"(acc[2 * p + 1][2]), "+f"(acc[2 * p + 1][3])
                : "r"(a0), "r"(a1), "r"(a2), "r"(a3), "r"(b2), "r"(b3));
        }
    }

    const int r0 = n0 + warp * 16 + g;
    const int r1 = r0 + 8;
#pragma unroll
    for (int nt = 0; nt < 8; nt++) {
        int col = nt * 8 + tg * 2;
        if (r0 < N) {
            __half2 h = __floats2half2_rn(acc[nt][0], acc[nt][1]);
            *reinterpret_cast<__half2*>(Yh_out + (size_t)r0 * 64 + col) = h;
        }
        if (r1 < N) {
            __half2 h = __floats2half2_rn(acc[nt][2], acc[nt][3]);
            *reinterpret_cast<__half2*>(Yh_out + (size_t)r1 * 64 + col) = h;
        }
    }
#pragma unroll
    for (int nt = 8; nt < 16; nt++) {
        int col = (nt - 8) * 8 + tg * 2;
        float bx = bls[col], by = bls[col + 1];
        if (r0 < N) {
            __half2 h = __floats2half2_rn(acc[nt][0] + bx, acc[nt][1] + by);
            *reinterpret_cast<__half2*>(selfh_out + (size_t)r0 * 64 + col) = h;
        }
        if (r1 < N) {
            __half2 h = __floats2half2_rn(acc[nt][2] + bx, acc[nt][3] + by);
            *reinterpret_cast<__half2*>(selfh_out + (size_t)r1 * 64 + col) = h;
        }
    }
}

// ---------------------------------------------------------------------------
// fused head: agg(layer 2) -> smem h tile -> head MLP -> out  (4 CTAs/SM)
// ---------------------------------------------------------------------------
__global__ __launch_bounds__(256, 4)
void fused_head(const int* __restrict__ rowptr, const int* __restrict__ csrc,
                const __half* __restrict__ Yh_in, const __half* __restrict__ selfh_in,
                const float* __restrict__ gamma, const float* __restrict__ beta,
                const float* __restrict__ mean, const float* __restrict__ var,
                const float* __restrict__ W1, const float* __restrict__ b1,
                const float* __restrict__ W2, const float* __restrict__ b2,
                float* __restrict__ out, int N) {
    constexpr int LDA = 72;
    extern __shared__ __half sm[];
    __half* As = sm;                                 // [128][72]
    float* w1t = (float*)(sm + 128 * LDA);           // [64][32]
    float* b1s = w1t + 64 * 32;
    float* w2s = b1s + 32;
    float* b2s = w2s + 32;

    const int t = threadIdx.x;
    const int warp = t >> 5, lane = t & 31;
    const int n0 = blockIdx.x * 128;
    const int sl = t & 7;
    const unsigned smask = 0xffu << (t & 24);

    for (int idx = t; idx < 64 * 32; idx += 256) {
        int k = idx >> 5, o = idx & 31;
        w1t[idx] = W1[o * 64 + k];
    }
    if (t < 32) { b1s[t] = b1[t]; w2s[t] = W2[t]; }
    if (t == 0) b2s[0] = b2[0];

    const uint4* Y4 = reinterpret_cast<const uint4*>(Yh_in);
#pragma unroll
    for (int r = 0; r < 4; r++) {
        int nl = r * 32 + (t >> 3);
        int node = n0 + nl;
        if (node < N) {
            int beg = rowptr[node], end = rowptr[node + 1];
            float sums[8];
            gather_node(Y4, csrc, beg, end, sl, smask, sums);
            float invd = 1.f / fmaxf((float)(end - beg), 1.f);
            uint4 pk = finalize_node(sums, invd, selfh_in, gamma, beta, mean, var,
                                     (size_t)node, 8 * sl);
            *reinterpret_cast<uint4*>(&As[nl * LDA + 8 * sl]) = pk;
        }
    }
    __syncthreads();

    for (int r = 0; r < 16; r++) {
        int nl = r * 8 + warp;
        int n = n0 + nl;
        if (n >= N) continue;
        __half2 raw = *reinterpret_cast<const __half2*>(&As[nl * LDA + lane * 2]);
        float2 hv = __half22float2(raw);
        float acc = 0.f;
#pragma unroll
        for (int q = 0; q < 32; q++) {
            float h0 = __shfl_sync(0xffffffffu, hv.x, q);
            float h1 = __shfl_sync(0xffffffffu, hv.y, q);
            acc += h0 * w1t[(2 * q) * 32 + lane];
            acc += h1 * w1t[(2 * q + 1) * 32 + lane];
        }
        float p = fmaxf(acc + b1s[lane], 0.f) * w2s[lane];
#pragma unroll
        for (int off = 16; off > 0; off >>= 1)
            p += __shfl_down_sync(0xffffffffu, p, off);
        if (lane == 0) out[n] = p + b2s[0];
    }
}

// ---------------------------------------------------------------------------
extern "C" void kernel_launch(void* const* d_in, const int* in_sizes, int n_in,
                              void* d_out, int out_size) {
    const float* x   = (const float*)d_in[0];
    const int*   ei  = (const int*)d_in[1];
    const float* Wl0 = (const float*)d_in[2];
    const float* Wr0 = (const float*)d_in[3];
    const float* bl0 = (const float*)d_in[4];
    const float* Wl1 = (const float*)d_in[5];
    const float* Wr1 = (const float*)d_in[6];
    const float* bl1 = (const float*)d_in[7];
    const float* Wl2 = (const float*)d_in[8];
    const float* Wr2 = (const float*)d_in[9];
    const float* bl2 = (const float*)d_in[10];
    const float* bng = (const float*)d_in[11];
    const float* bnb = (const float*)d_in[12];
    const float* bnm = (const float*)d_in[13];
    const float* bnv = (const float*)d_in[14];
    const float* hW1 = (const float*)d_in[15];
    const float* hb1 = (const float*)d_in[16];
    const float* hW2 = (const float*)d_in[17];
    const float* hb2 = (const float*)d_in[18];

    const int N = in_sizes[0] / 128;
    const int E = in_sizes[1] / 2;
    const int* src = ei;
    const int* dst = ei + E;

    __half *yhA, *selfhA, *yhB, *selfhB, *w0, *w1, *w2;
    int *deg, *rowptr, *cursor, *csrc;
    unsigned* state;
    cudaGetSymbolAddress((void**)&yhA,    g_yhA);
    cudaGetSymbolAddress((void**)&selfhA, g_selfhA);
    cudaGetSymbolAddress((void**)&yhB,    g_yhB);
    cudaGetSymbolAddress((void**)&selfhB, g_selfhB);
    cudaGetSymbolAddress((void**)&deg,    g_deg);
    cudaGetSymbolAddress((void**)&rowptr, g_rowptr);
    cudaGetSymbolAddress((void**)&cursor, g_cursor);
    cudaGetSymbolAddress((void**)&csrc,   g_csrc);
    cudaGetSymbolAddress((void**)&state,  g_state);
    cudaGetSymbolAddress((void**)&w0,     g_w0);
    cudaGetSymbolAddress((void**)&w1,     g_w1);
    cudaGetSymbolAddress((void**)&w2,     g_w2);

    const int SMEM_CS128 = 192 * (128 + 8) * 2 + 256;         // 52480
    const int SMEM_FL    = 2 * 128 * 72 * 2 + 256;            // 37120
    const int SMEM_FH    = 128 * 72 * 2 + (64 * 32 + 65) * 4; // 26948
    cudaFuncSetAttribute((const void*)gemm_cs<float, 128>,
                         cudaFuncAttributeMaxDynamicSharedMemorySize, SMEM_CS128);
    cudaFuncSetAttribute((const void*)fused_layer,
                         cudaFuncAttributeMaxDynamicSharedMemorySize, SMEM_FL);
    cudaFuncSetAttribute((const void*)fused_head,
                         cudaFuncAttributeMaxDynamicSharedMemorySize, SMEM_FH);

    const int gblocks = (N + 127) / 128;
    const dim3 ggrid(gblocks, 2);
    const int e4blocks = ((E + 3) / 4 + 255) / 256;
    const int nscan    = (N + 1023) / 1024;

    // zero-invariant protocol: deg/state are zero at entry (module-load init +
    // per-replay restoration inside scan_lookback / gemm_cs).
    // #1 prep+deg, #2 scan, #3 scatter, #4 gemm128 (profiled slot)
    prep_deg<<<e4blocks, 256>>>(Wl0, Wr0, Wl1, Wr1, Wl2, Wr2,
                                w0, w1, w2, dst, deg, E);
    scan_lookback<<<nscan, 256>>>(deg, rowptr, cursor, state, N);
    scatter_kernel<<<e4blocks, 256>>>(src, dst, cursor, csrc, E);
    gemm_cs<float, 128><<<ggrid, 256, SMEM_CS128>>>(x, w0, bl0, yhA, selfhA, N, state);

    // fused layers: agg0+gemm1 (A->B), agg1+gemm2 (B->A), agg2+head (A->out)
    fused_layer<<<gblocks, 256, SMEM_FL>>>(rowptr, csrc, yhA, selfhA,
                                           bng, bnb, bnm, bnv,
                                           w1, bl1, yhB, selfhB, N);
    fused_layer<<<gblocks, 256, SMEM_FL>>>(rowptr, csrc, yhB, selfhB,
                                           bng + 64, bnb + 64, bnm + 64, bnv + 64,
                                           w2, bl2, yhA, selfhA, N);
    fused_head<<<gblocks, 256, SMEM_FH>>>(rowptr, csrc, yhA, selfhA,
                                          bng + 128, bnb + 128, bnm + 128, bnv + 128,
                                          hW1, hb1, hW2, hb2, (float*)d_out, N);
}